// round 1
// baseline (speedup 1.0000x reference)
#include <cuda_runtime.h>

// ---------------------------------------------------------------------------
// TensorDense: out = relu(x @ W + bias) where W is the explicit 4096x4096
// matrix implied by the tensor-train cores:
//   W[(i,j,k),(a,b,c)] = sum_q ( sum_p c1[i,a,p]*c2[j,b,p,q] ) * c3[k,c,q]
// FLOPs: ~1.2 GF to build W + 68.7 GF GEMM (vs ~292 GF for direct TT path).
// ---------------------------------------------------------------------------

#define MODE 16
#define BOND0 32
#define BOND1 32
#define KDIM 4096   // = 16*16*16 input modes
#define NDIM 4096   // = 16*16*16 output modes
#define BATCH 2048

// 64 MB scratch for the materialized weight matrix (allowed: __device__ global)
__device__ float g_W[(size_t)KDIM * NDIM];

// ---------------------------------------------------------------------------
// Kernel 1: build W. One CTA per (i, j, a, b) quad (65536 CTAs, 256 threads).
//   step 1: 256 threads stage c2[j,b,:,:] (1024 floats) into shared
//   step 2: 32 threads compute W12[q] = sum_p c1[i,a,p] * c2[j,b,p,q]
//   step 3: each thread (k, c) computes W element = sum_q W12[q]*c3[k,c,q]
// ---------------------------------------------------------------------------
__global__ void build_w_kernel(const float* __restrict__ c1,
                               const float* __restrict__ c2,
                               const float* __restrict__ c3) {
    __shared__ float sC2[BOND0 * BOND1];
    __shared__ float sW12[BOND1];

    const int bid = blockIdx.x;
    const int i = (bid >> 12) & 15;
    const int j = (bid >> 8) & 15;
    const int a = (bid >> 4) & 15;
    const int b = bid & 15;
    const int tid = threadIdx.x;

    // stage c2 slice: c2 is [j][b][p][q], slice is contiguous 1024 floats
    const float4* c2slice =
        reinterpret_cast<const float4*>(c2 + (size_t)(j * MODE + b) * BOND0 * BOND1);
    reinterpret_cast<float4*>(sC2)[tid] = c2slice[tid];
    __syncthreads();

    // W12[q] = sum_p c1[i,a,p] * c2[j,b,p,q]
    if (tid < BOND1) {
        const float* c1row = c1 + (i * MODE + a) * BOND0;
        float w = 0.f;
#pragma unroll
        for (int p = 0; p < BOND0; ++p)
            w = fmaf(c1row[p], sC2[p * BOND1 + tid], w);
        sW12[tid] = w;
    }
    __syncthreads();

    // thread -> (k, c); W[(i,j,k),(a,b,c)] = sum_q W12[q] * c3[k,c,q]
    const int k = tid >> 4;
    const int c = tid & 15;
    const float4* c3row =
        reinterpret_cast<const float4*>(c3 + (k * MODE + c) * BOND1);
    float acc = 0.f;
#pragma unroll
    for (int q4 = 0; q4 < BOND1 / 4; ++q4) {
        float4 v = c3row[q4];
        acc = fmaf(sW12[q4 * 4 + 0], v.x, acc);
        acc = fmaf(sW12[q4 * 4 + 1], v.y, acc);
        acc = fmaf(sW12[q4 * 4 + 2], v.z, acc);
        acc = fmaf(sW12[q4 * 4 + 3], v.w, acc);
    }
    const int row = (i * MODE + j) * MODE + k;
    const int col = (a * MODE + b) * MODE + c;
    g_W[(size_t)row * NDIM + col] = acc;
}

// ---------------------------------------------------------------------------
// Kernel 2: C = relu(A @ W + bias). Classic double-buffered SGEMM.
// 128x128 CTA tile, BK=8, 256 threads, 8x8 register micro-tile.
// ---------------------------------------------------------------------------
#define BM 128
#define BN 128
#define BK 8
#define TM 8
#define TN 8

__global__ __launch_bounds__(256, 2)
void sgemm_bias_relu_kernel(const float* __restrict__ A,     // [2048, 4096]
                            const float* __restrict__ bias,  // [4096]
                            float* __restrict__ C) {         // [2048, 4096]
    __shared__ float As[2][BK][BM];
    __shared__ float Bs[2][BK][BN];

    const float* __restrict__ B = g_W;

    const int tid = threadIdx.x;
    const int tx = tid & 15;   // column group
    const int ty = tid >> 4;   // row group

    const int blockRow = blockIdx.y * BM;
    const int blockCol = blockIdx.x * BN;

    // A tile load mapping: 128 rows x 8 cols -> 256 x float4
    const int aRow = tid >> 1;
    const int aCol = (tid & 1) * 4;
    // B tile load mapping: 8 rows x 128 cols -> 256 x float4
    const int bRow = tid >> 5;
    const int bCol = (tid & 31) * 4;

    const float* Aptr = A + (size_t)(blockRow + aRow) * KDIM + aCol;
    const float* Bptr = B + (size_t)bRow * NDIM + blockCol + bCol;

    float acc[TM][TN];
#pragma unroll
    for (int ii = 0; ii < TM; ++ii)
#pragma unroll
        for (int jj = 0; jj < TN; ++jj) acc[ii][jj] = 0.f;

    // preload tile 0
    float4 a4 = *reinterpret_cast<const float4*>(Aptr);
    float4 b4 = *reinterpret_cast<const float4*>(Bptr);
    As[0][aCol + 0][aRow] = a4.x;
    As[0][aCol + 1][aRow] = a4.y;
    As[0][aCol + 2][aRow] = a4.z;
    As[0][aCol + 3][aRow] = a4.w;
    *reinterpret_cast<float4*>(&Bs[0][bRow][bCol]) = b4;
    __syncthreads();

    const int numTiles = KDIM / BK;  // 512
    int cur = 0;

    for (int t = 0; t < numTiles; ++t) {
        const bool hasNext = (t + 1 < numTiles);
        if (hasNext) {
            a4 = *reinterpret_cast<const float4*>(Aptr + (t + 1) * BK);
            b4 = *reinterpret_cast<const float4*>(Bptr + (size_t)(t + 1) * BK * NDIM);
        }

#pragma unroll
        for (int kk = 0; kk < BK; ++kk) {
            float aFrag[TM], bFrag[TN];
            *reinterpret_cast<float4*>(&aFrag[0]) =
                *reinterpret_cast<const float4*>(&As[cur][kk][ty * TM]);
            *reinterpret_cast<float4*>(&aFrag[4]) =
                *reinterpret_cast<const float4*>(&As[cur][kk][ty * TM + 4]);
            *reinterpret_cast<float4*>(&bFrag[0]) =
                *reinterpret_cast<const float4*>(&Bs[cur][kk][tx * TN]);
            *reinterpret_cast<float4*>(&bFrag[4]) =
                *reinterpret_cast<const float4*>(&Bs[cur][kk][tx * TN + 4]);
#pragma unroll
            for (int ii = 0; ii < TM; ++ii)
#pragma unroll
                for (int jj = 0; jj < TN; ++jj)
                    acc[ii][jj] = fmaf(aFrag[ii], bFrag[jj], acc[ii][jj]);
        }

        if (hasNext) {
            const int nxt = cur ^ 1;
            As[nxt][aCol + 0][aRow] = a4.x;
            As[nxt][aCol + 1][aRow] = a4.y;
            As[nxt][aCol + 2][aRow] = a4.z;
            As[nxt][aCol + 3][aRow] = a4.w;
            *reinterpret_cast<float4*>(&Bs[nxt][bRow][bCol]) = b4;
            __syncthreads();
            cur = nxt;
        }
    }

    // epilogue: bias + relu, vectorized stores
    const int row0 = blockRow + ty * TM;
    const int col0 = blockCol + tx * TN;
#pragma unroll
    for (int ii = 0; ii < TM; ++ii) {
#pragma unroll
        for (int j4 = 0; j4 < TN / 4; ++j4) {
            const int cbase = col0 + j4 * 4;
            float4 o;
            o.x = fmaxf(acc[ii][j4 * 4 + 0] + bias[cbase + 0], 0.f);
            o.y = fmaxf(acc[ii][j4 * 4 + 1] + bias[cbase + 1], 0.f);
            o.z = fmaxf(acc[ii][j4 * 4 + 2] + bias[cbase + 2], 0.f);
            o.w = fmaxf(acc[ii][j4 * 4 + 3] + bias[cbase + 3], 0.f);
            *reinterpret_cast<float4*>(&C[(size_t)(row0 + ii) * NDIM + cbase]) = o;
        }
    }
}

// ---------------------------------------------------------------------------
// Launch
// ---------------------------------------------------------------------------
extern "C" void kernel_launch(void* const* d_in, const int* in_sizes, int n_in,
                              void* d_out, int out_size) {
    const float* x    = (const float*)d_in[0];  // [2048, 4096]
    const float* c1   = (const float*)d_in[1];  // [16, 16, 32]
    const float* c2   = (const float*)d_in[2];  // [16, 16, 32, 32]
    const float* c3   = (const float*)d_in[3];  // [16, 16, 32]
    const float* bias = (const float*)d_in[4];  // [16, 16, 16] -> 4096
    float* out = (float*)d_out;                 // [2048, 4096]

    (void)in_sizes; (void)n_in; (void)out_size;

    // Build W (16^4 = 65536 CTAs over (i, j, a, b))
    build_w_kernel<<<MODE * MODE * MODE * MODE, 256>>>(c1, c2, c3);

    // GEMM: grid covers N=4096 (x) and M=2048 (y) in 128x128 tiles
    dim3 grid(NDIM / BN, BATCH / BM);
    sgemm_bias_relu_kernel<<<grid, 256>>>(x, bias, out);
}

// round 3
// speedup vs baseline: 1.5825x; 1.5825x over previous
#include <cuda_runtime.h>
#include <cuda_bf16.h>
#include <cstdint>

// ============================================================================
// TensorDense via explicit-W:  out = relu(x @ W + bias)
//   W[(i,j,k),(a,b,c)] = sum_q (sum_p c1[i,a,p] c2[j,b,p,q]) c3[k,c,q]
// GEMM on legacy tensor cores (mma.sync bf16, fp32 accum) with split
// precision: x = xh+xl, W = Wh+Wl, C ~= xh*Wh + xh*Wl + xl*Wh.
// (tcgen05 is unavailable: harness PTX targets sm_103 without the 'a' suffix.)
// ============================================================================

#define MODE 16
#define KDIM 4096
#define NDIM 4096
#define BATCH 2048

__device__ __nv_bfloat16 g_x_hi[(size_t)BATCH * KDIM];
__device__ __nv_bfloat16 g_x_lo[(size_t)BATCH * KDIM];
__device__ __nv_bfloat16 g_Wt_hi[(size_t)NDIM * KDIM];   // [n][k]
__device__ __nv_bfloat16 g_Wt_lo[(size_t)NDIM * KDIM];

// ---------------------------------------------------------------------------
// small PTX helpers (all sm_80/sm_90-era, no arch-'a' features)
// ---------------------------------------------------------------------------
__device__ __forceinline__ uint32_t smem_u32(const void* p) {
    uint32_t a;
    asm("{ .reg .u64 t; cvta.to.shared.u64 t, %1; cvt.u32.u64 %0, t; }"
        : "=r"(a) : "l"(p));
    return a;
}

__device__ __forceinline__ void cp_async16(uint32_t s, const void* g) {
    asm volatile("cp.async.cg.shared.global [%0], [%1], 16;" :: "r"(s), "l"(g));
}
#define CP_COMMIT() asm volatile("cp.async.commit_group;" ::: "memory")
#define CP_WAIT1()  asm volatile("cp.async.wait_group 1;"  ::: "memory")
#define CP_WAIT0()  asm volatile("cp.async.wait_group 0;"  ::: "memory")

__device__ __forceinline__ void ldmx4(uint32_t* r, uint32_t addr) {
    asm volatile("ldmatrix.sync.aligned.m8n8.x4.shared.b16 {%0,%1,%2,%3}, [%4];"
                 : "=r"(r[0]), "=r"(r[1]), "=r"(r[2]), "=r"(r[3]) : "r"(addr));
}

__device__ __forceinline__ void mma16816(float* c, const uint32_t* a,
                                         uint32_t b0, uint32_t b1) {
    asm volatile(
        "mma.sync.aligned.m16n8k16.row.col.f32.bf16.bf16.f32 "
        "{%0,%1,%2,%3}, {%4,%5,%6,%7}, {%8,%9}, {%0,%1,%2,%3};"
        : "+f"(c[0]), "+f"(c[1]), "+f"(c[2]), "+f"(c[3])
        : "r"(a[0]), "r"(a[1]), "r"(a[2]), "r"(a[3]), "r"(b0), "r"(b1));
}

// ---------------------------------------------------------------------------
// Kernel 1: build W transposed, split into bf16 hi/lo. CTA per (i,j,a,b).
// ---------------------------------------------------------------------------
__global__ void build_w_kernel(const float* __restrict__ c1,
                               const float* __restrict__ c2,
                               const float* __restrict__ c3) {
    __shared__ float sC2[1024];
    __shared__ float sW12[32];

    const int bid = blockIdx.x;
    const int i = (bid >> 12) & 15;
    const int j = (bid >> 8) & 15;
    const int a = (bid >> 4) & 15;
    const int b = bid & 15;
    const int tid = threadIdx.x;

    reinterpret_cast<float4*>(sC2)[tid] =
        reinterpret_cast<const float4*>(c2 + (size_t)(j * MODE + b) * 1024)[tid];
    __syncthreads();

    if (tid < 32) {
        const float* c1row = c1 + (i * MODE + a) * 32;
        float w = 0.f;
#pragma unroll
        for (int p = 0; p < 32; ++p)
            w = fmaf(c1row[p], sC2[p * 32 + tid], w);
        sW12[tid] = w;
    }
    __syncthreads();

    const int c = tid >> 4;       // output mode c
    const int kz = tid & 15;      // input mode z (contiguous k writes)
    const float4* c3row = reinterpret_cast<const float4*>(c3 + (kz * MODE + c) * 32);
    float acc = 0.f;
#pragma unroll
    for (int q4 = 0; q4 < 8; ++q4) {
        float4 v = c3row[q4];
        acc = fmaf(sW12[q4 * 4 + 0], v.x, acc);
        acc = fmaf(sW12[q4 * 4 + 1], v.y, acc);
        acc = fmaf(sW12[q4 * 4 + 2], v.z, acc);
        acc = fmaf(sW12[q4 * 4 + 3], v.w, acc);
    }
    const int col = (a * MODE + b) * MODE + c;    // n
    const int row = (i * MODE + j) * MODE + kz;   // k
    __nv_bfloat16 hi = __float2bfloat16(acc);
    __nv_bfloat16 lo = __float2bfloat16(acc - __bfloat162float(hi));
    g_Wt_hi[(size_t)col * KDIM + row] = hi;
    g_Wt_lo[(size_t)col * KDIM + row] = lo;
}

// ---------------------------------------------------------------------------
// Kernel 2: split x into bf16 hi/lo.
// ---------------------------------------------------------------------------
__global__ void split_x_kernel(const float* __restrict__ x) {
    const size_t t = (size_t)blockIdx.x * 256 + threadIdx.x;
    float4 v = reinterpret_cast<const float4*>(x)[t];
    __nv_bfloat162 h01 = __floats2bfloat162_rn(v.x, v.y);
    __nv_bfloat162 h23 = __floats2bfloat162_rn(v.z, v.w);
    float2 f01 = __bfloat1622float2(h01);
    float2 f23 = __bfloat1622float2(h23);
    __nv_bfloat162 l01 = __floats2bfloat162_rn(v.x - f01.x, v.y - f01.y);
    __nv_bfloat162 l23 = __floats2bfloat162_rn(v.z - f23.x, v.w - f23.y);
    reinterpret_cast<__nv_bfloat162*>(g_x_hi)[t * 2 + 0] = h01;
    reinterpret_cast<__nv_bfloat162*>(g_x_hi)[t * 2 + 1] = h23;
    reinterpret_cast<__nv_bfloat162*>(g_x_lo)[t * 2 + 0] = l01;
    reinterpret_cast<__nv_bfloat162*>(g_x_lo)[t * 2 + 1] = l23;
}

// ---------------------------------------------------------------------------
// Kernel 3: mma.sync bf16x3 GEMM.
// CTA tile 128x128, BK=32, 8 warps (2 m x 4 n), warp tile 64x32.
// SMEM rows padded to 80B (conflict-free ldmatrix: banks (r*20)%32 distinct).
// ---------------------------------------------------------------------------
#define BM 128
#define BN 128
#define ROWB 80                      // padded row stride in bytes (32 bf16 data)
#define ARR_BYTES (128 * ROWB)       // 10240 per array
#define STAGE_BYTES (4 * ARR_BYTES)  // Ah | Al | Bh | Bl = 40960
#define DYN_BYTES (2 * STAGE_BYTES)  // 81920

__global__ __launch_bounds__(256, 1)
void tt_gemm_bf16x3(const float* __restrict__ bias, float* __restrict__ C) {
    extern __shared__ __align__(16) char dyn[];
    const uint32_t dynU = smem_u32(dyn);

    const int tid = threadIdx.x;
    const int wid = tid >> 5;
    const int lid = tid & 31;
    const int warp_m = wid & 1;      // 0..1  (64 rows each)
    const int warp_n = wid >> 1;     // 0..3  (32 cols each)
    const int m0 = blockIdx.y * BM;
    const int n0 = blockIdx.x * BN;

    const char* xh = (const char*)g_x_hi;
    const char* xl = (const char*)g_x_lo;
    const char* wh = (const char*)g_Wt_hi;
    const char* wl = (const char*)g_Wt_lo;

    // global/smem load mapping: 2 x 16B chunks per thread per array
    // ci = u*256+tid -> r = ci>>2 (row 0..127), ch = ci&3 (16B chunk in 64B row)
    int r0c = tid >> 2, ch0 = (tid & 3) * 16;
    int r1c = (256 + tid) >> 2, ch1 = ((256 + tid) & 3) * 16;
    const uint32_t s0 = (uint32_t)(r0c * ROWB + ch0);
    const uint32_t s1 = (uint32_t)(r1c * ROWB + ch1);
    const size_t gA0 = (size_t)(m0 + r0c) * (KDIM * 2) + ch0;
    const size_t gA1 = (size_t)(m0 + r1c) * (KDIM * 2) + ch1;
    const size_t gB0 = (size_t)(n0 + r0c) * (KDIM * 2) + ch0;
    const size_t gB1 = (size_t)(n0 + r1c) * (KDIM * 2) + ch1;

    float acc[4][4][4];
#pragma unroll
    for (int a = 0; a < 4; ++a)
#pragma unroll
        for (int b = 0; b < 4; ++b)
#pragma unroll
            for (int c = 0; c < 4; ++c) acc[a][b][c] = 0.f;

    // ldmatrix per-lane base offsets (canonical 16x16 pattern)
    const uint32_t lmRow = (uint32_t)(lid & 15);
    const uint32_t lmCol = (uint32_t)((lid >> 4) * 16);
    const uint32_t aLM = (uint32_t)((warp_m * 64 + lmRow) * ROWB) + lmCol;
    const uint32_t bLM = (uint32_t)((warp_n * 32 + lmRow) * ROWB) + lmCol;

    auto load_stage = [&](int kt) {
        const uint32_t sb = dynU + (uint32_t)(kt & 1) * STAGE_BYTES;
        const size_t ko = (size_t)kt * 64;   // 32 bf16 = 64 bytes along k
        cp_async16(sb + s0,                    xh + gA0 + ko);
        cp_async16(sb + s1,                    xh + gA1 + ko);
        cp_async16(sb + ARR_BYTES + s0,        xl + gA0 + ko);
        cp_async16(sb + ARR_BYTES + s1,        xl + gA1 + ko);
        cp_async16(sb + 2 * ARR_BYTES + s0,    wh + gB0 + ko);
        cp_async16(sb + 2 * ARR_BYTES + s1,    wh + gB1 + ko);
        cp_async16(sb + 3 * ARR_BYTES + s0,    wl + gB0 + ko);
        cp_async16(sb + 3 * ARR_BYTES + s1,    wl + gB1 + ko);
    };

    load_stage(0);
    CP_COMMIT();

    const int numK = KDIM / 32;      // 128 stages
    for (int kt = 0; kt < numK; ++kt) {
        if (kt + 1 < numK) {
            load_stage(kt + 1);
            CP_COMMIT();
            CP_WAIT1();
        } else {
            CP_WAIT0();
        }
        __syncthreads();

        const uint32_t sb = dynU + (uint32_t)(kt & 1) * STAGE_BYTES;
        const uint32_t aB = sb + aLM;
        const uint32_t bB = sb + 2 * ARR_BYTES + bLM;

#pragma unroll
        for (int ks = 0; ks < 2; ++ks) {             // two k16 steps
            const uint32_t kb = (uint32_t)(ks * 32); // 16 bf16 = 32B
            uint32_t ah[4][4], al[4][4];
#pragma unroll
            for (int mt = 0; mt < 4; ++mt) {
                ldmx4(ah[mt], aB + (uint32_t)(mt * 16 * ROWB) + kb);
                ldmx4(al[mt], aB + ARR_BYTES + (uint32_t)(mt * 16 * ROWB) + kb);
            }
            uint32_t bh[2][4], bl[2][4];
#pragma unroll
            for (int bt = 0; bt < 2; ++bt) {
                ldmx4(bh[bt], bB + (uint32_t)(bt * 16 * ROWB) + kb);
                ldmx4(bl[bt], bB + ARR_BYTES + (uint32_t)(bt * 16 * ROWB) + kb);
            }
#pragma unroll
            for (int mt = 0; mt < 4; ++mt) {
#pragma unroll
                for (int nt = 0; nt < 4; ++nt) {
                    const int bt = nt >> 1, o = nt & 1;
                    mma16816(acc[mt][nt], ah[mt], bh[bt][o], bh[bt][o + 2]);
                    mma16816(acc[mt][nt], ah[mt], bl[bt][o], bl[bt][o + 2]);
                    mma16816(acc[mt][nt], al[mt], bh[bt][o], bh[bt][o + 2]);
                }
            }
        }
        __syncthreads();
    }

    // --- epilogue: bias + relu, float2 stores ---
    const int g = lid >> 2, t4 = lid & 3;
    float bb[4][2];
#pragma unroll
    for (int nt = 0; nt < 4; ++nt) {
        const int col = n0 + warp_n * 32 + nt * 8 + t4 * 2;
        bb[nt][0] = bias[col];
        bb[nt][1] = bias[col + 1];
    }
#pragma unroll
    for (int mt = 0; mt < 4; ++mt) {
        const int row = m0 + warp_m * 64 + mt * 16 + g;
#pragma unroll
        for (int nt = 0; nt < 4; ++nt) {
            const int col = n0 + warp_n * 32 + nt * 8 + t4 * 2;
            float2 v0, v1;
            v0.x = fmaxf(acc[mt][nt][0] + bb[nt][0], 0.f);
            v0.y = fmaxf(acc[mt][nt][1] + bb[nt][1], 0.f);
            v1.x = fmaxf(acc[mt][nt][2] + bb[nt][0], 0.f);
            v1.y = fmaxf(acc[mt][nt][3] + bb[nt][1], 0.f);
            *reinterpret_cast<float2*>(&C[(size_t)row * NDIM + col]) = v0;
            *reinterpret_cast<float2*>(&C[(size_t)(row + 8) * NDIM + col]) = v1;
        }
    }
}

// ---------------------------------------------------------------------------
// Launch
// ---------------------------------------------------------------------------
extern "C" void kernel_launch(void* const* d_in, const int* in_sizes, int n_in,
                              void* d_out, int out_size) {
    const float* x    = (const float*)d_in[0];
    const float* c1   = (const float*)d_in[1];
    const float* c2   = (const float*)d_in[2];
    const float* c3   = (const float*)d_in[3];
    const float* bias = (const float*)d_in[4];
    float* out = (float*)d_out;
    (void)in_sizes; (void)n_in; (void)out_size;

    cudaFuncSetAttribute(tt_gemm_bf16x3,
                         cudaFuncAttributeMaxDynamicSharedMemorySize, DYN_BYTES);

    build_w_kernel<<<MODE * MODE * MODE * MODE, 256>>>(c1, c2, c3);
    split_x_kernel<<<(BATCH * KDIM) / (4 * 256), 256>>>(x);

    dim3 grid(NDIM / BN, BATCH / BM);   // (32, 16) = 512 CTAs
    tt_gemm_bf16x3<<<grid, 256, DYN_BYTES>>>(bias, out);
}